// round 11
// baseline (speedup 1.0000x reference)
#include <cuda_runtime.h>
#include <cuda_fp16.h>
#include <cstdint>

#define NMAX 150016
#define EMAX 2400000
#define SCAN_BLK 1024

__device__ int   g_cnt[NMAX];      // in-degree (real edges only)
__device__ int   g_rp[NMAX];       // CSR row_ptr
__device__ int   g_cur[NMAX];      // fill cursors
__device__ int   g_bsum[1024];
__device__ int   g_csr[EMAX];      // src indices bucketed by dst
__device__ float g_dis[NMAX];
__device__ __align__(16) __half g_h1[NMAX * 32];  // layer-1 h' (scaled, fp16)
__device__ __align__(16) __half g_h2[NMAX * 32];  // layer-2 h' (scaled, fp16)
__device__ float g_h3[NMAX];

struct alignas(8) half4 { __half2 a, b; };

// ---------------------------------------------------------------- prep

__global__ void cnt_init_k(int N) {
    int i = blockIdx.x * blockDim.x + threadIdx.x;
    if (i < N) g_cnt[i] = 0;
}

__global__ void edge_cnt_k(const int* __restrict__ ei, int E, int N) {
    int e = blockIdx.x * blockDim.x + threadIdx.x;
    if (e >= E) return;
    int d = ei[E + e];
    if ((unsigned)d >= (unsigned)N) d = 0;
    atomicAdd(&g_cnt[d], 1);
}

// scan phase 1 + dis (fused)
__global__ void scan1_k(int N) {
    __shared__ int sh[SCAN_BLK];
    int i = blockIdx.x * SCAN_BLK + threadIdx.x;
    int v = (i < N) ? g_cnt[i] : 0;
    if (i < N) g_dis[i] = rsqrtf((float)(v + 1));
    sh[threadIdx.x] = v;
    __syncthreads();
    for (int off = 1; off < SCAN_BLK; off <<= 1) {
        int t = (threadIdx.x >= off) ? sh[threadIdx.x - off] : 0;
        __syncthreads();
        sh[threadIdx.x] += t;
        __syncthreads();
    }
    if (i < N) g_rp[i] = sh[threadIdx.x] - v;   // block-local exclusive
    if (threadIdx.x == SCAN_BLK - 1) g_bsum[blockIdx.x] = sh[threadIdx.x];
}

// scan2+scan3 merged: every block redundantly scans the (<=256) block sums.
__global__ void scan3_k(int N) {
    __shared__ int sb[256];
    int nb = gridDim.x;
    int t = threadIdx.x;
    if (t < 256) sb[t] = (t < nb) ? g_bsum[t] : 0;
    __syncthreads();
    for (int off = 1; off < 256; off <<= 1) {
        int v = (t < 256 && t >= off) ? sb[t - off] : 0;
        __syncthreads();
        if (t < 256) sb[t] += v;
        __syncthreads();
    }
    int i = blockIdx.x * SCAN_BLK + t;
    if (i < N) {
        int boff = (blockIdx.x > 0) ? sb[blockIdx.x - 1] : 0;
        int r = g_rp[i] + boff;
        g_rp[i]  = r;
        g_cur[i] = r;
    }
}

__global__ void fill_k(const int* __restrict__ ei, int E, int N) {
    int e = blockIdx.x * blockDim.x + threadIdx.x;
    if (e >= E) return;
    int s = ei[e];
    int d = ei[E + e];
    if ((unsigned)s >= (unsigned)N) s = 0;
    if ((unsigned)d >= (unsigned)N) d = 0;
    int pos = atomicAdd(&g_cur[d], 1);
    g_csr[pos] = s;
}

// ---------------------------------------------------------------- warp gather-sum helper
// Lane-parallel over 32 cols; coalesced 32-index load + shfl distribute, 4-deep MLP.

__device__ __forceinline__ float warp_gather_sum(
    const __half* __restrict__ hp,   // h + lane
    int node, int beg, int cnt)
{
    float a0 = __half2float(hp[(size_t)node * 32]);  // self term
    float a1 = 0.f, a2 = 0.f, a3 = 0.f;
    int lane = threadIdx.x & 31;
    for (int j = 0; j < cnt; j += 32) {
        int m = cnt - j; if (m > 32) m = 32;
        int idx = (lane < m) ? __ldg(&g_csr[beg + j + lane]) : 0;
        int k = 0;
        for (; k + 4 <= m; k += 4) {
            int s0 = __shfl_sync(0xffffffffu, idx, k + 0);
            int s1 = __shfl_sync(0xffffffffu, idx, k + 1);
            int s2 = __shfl_sync(0xffffffffu, idx, k + 2);
            int s3 = __shfl_sync(0xffffffffu, idx, k + 3);
            a0 += __half2float(__ldg(&hp[(size_t)s0 * 32]));
            a1 += __half2float(__ldg(&hp[(size_t)s1 * 32]));
            a2 += __half2float(__ldg(&hp[(size_t)s2 * 32]));
            a3 += __half2float(__ldg(&hp[(size_t)s3 * 32]));
        }
        for (; k < m; ++k) {
            int s = __shfl_sync(0xffffffffu, idx, k);
            a0 += __half2float(__ldg(&hp[(size_t)s * 32]));
        }
    }
    return (a0 + a1) + (a2 + a3);
}

// ---------------------------------------------------------------- GEMM layer 1 (K=128)
// 256 threads, 128x32 tile, 4x4 microtile, cp.async 2-stage. h1' = (x@W1)*dis, fp16.

#define MMA4(i, XI, W0, W1, W2, W3)                            \
    acc[i].x = fmaf(XI.x, W0.x, acc[i].x);                     \
    acc[i].y = fmaf(XI.x, W0.y, acc[i].y);                     \
    acc[i].z = fmaf(XI.x, W0.z, acc[i].z);                     \
    acc[i].w = fmaf(XI.x, W0.w, acc[i].w);                     \
    acc[i].x = fmaf(XI.y, W1.x, acc[i].x);                     \
    acc[i].y = fmaf(XI.y, W1.y, acc[i].y);                     \
    acc[i].z = fmaf(XI.y, W1.z, acc[i].z);                     \
    acc[i].w = fmaf(XI.y, W1.w, acc[i].w);                     \
    acc[i].x = fmaf(XI.z, W2.x, acc[i].x);                     \
    acc[i].y = fmaf(XI.z, W2.y, acc[i].y);                     \
    acc[i].z = fmaf(XI.z, W2.z, acc[i].z);                     \
    acc[i].w = fmaf(XI.z, W2.w, acc[i].w);                     \
    acc[i].x = fmaf(XI.w, W3.x, acc[i].x);                     \
    acc[i].y = fmaf(XI.w, W3.y, acc[i].y);                     \
    acc[i].z = fmaf(XI.w, W3.z, acc[i].z);                     \
    acc[i].w = fmaf(XI.w, W3.w, acc[i].w);

__global__ void __launch_bounds__(256) gemm1_k(
    const float* __restrict__ A, const float* __restrict__ W,
    const float* __restrict__ dis, __half* __restrict__ out, int M)
{
    constexpr int K = 128, NCH = 4, XST = 36;
    __shared__ float ws[K][32];
    __shared__ float xs[2][128][XST];

    const int tid  = threadIdx.x;
    const int row0 = blockIdx.x * 128;
    const int tx = tid & 7;
    const int ty = tid >> 3;
    const int lr  = tid >> 3;
    const int lc4 = tid & 7;

    for (int i = tid; i < K * 8; i += 256)
        ((float4*)ws)[i] = ((const float4*)W)[i];

    float4 acc[4] = {{0,0,0,0},{0,0,0,0},{0,0,0,0},{0,0,0,0}};

    auto prefetch = [&](int c) {
        int buf = c & 1;
#pragma unroll
        for (int u = 0; u < 4; ++u) {
            int row = row0 + lr + u * 32;
            float* dst = &xs[buf][lr + u * 32][lc4 * 4];
            if (row < M) {
                unsigned sa = (unsigned)__cvta_generic_to_shared(dst);
                const float* src = A + (size_t)row * K + c * 32 + lc4 * 4;
                asm volatile("cp.async.cg.shared.global [%0], [%1], 16;"
                             :: "r"(sa), "l"(src));
            } else {
                *(float4*)dst = make_float4(0.f, 0.f, 0.f, 0.f);
            }
        }
        asm volatile("cp.async.commit_group;");
    };

    prefetch(0);
#pragma unroll
    for (int c = 0; c < NCH; ++c) {
        if (c + 1 < NCH) {
            prefetch(c + 1);
            asm volatile("cp.async.wait_group 1;");
        } else {
            asm volatile("cp.async.wait_group 0;");
        }
        __syncthreads();
        const float (*x)[XST] = xs[c & 1];
#pragma unroll
        for (int kq = 0; kq < 8; ++kq) {
            float4 w0 = *(const float4*)&ws[c * 32 + kq * 4 + 0][4 * tx];
            float4 w1 = *(const float4*)&ws[c * 32 + kq * 4 + 1][4 * tx];
            float4 w2 = *(const float4*)&ws[c * 32 + kq * 4 + 2][4 * tx];
            float4 w3 = *(const float4*)&ws[c * 32 + kq * 4 + 3][4 * tx];
            float4 x0 = *(const float4*)&x[4 * ty + 0][kq * 4];
            float4 x1 = *(const float4*)&x[4 * ty + 1][kq * 4];
            float4 x2 = *(const float4*)&x[4 * ty + 2][kq * 4];
            float4 x3 = *(const float4*)&x[4 * ty + 3][kq * 4];
            MMA4(0, x0, w0, w1, w2, w3)
            MMA4(1, x1, w0, w1, w2, w3)
            MMA4(2, x2, w0, w1, w2, w3)
            MMA4(3, x3, w0, w1, w2, w3)
        }
        __syncthreads();
    }

#pragma unroll
    for (int i = 0; i < 4; ++i) {
        int row = row0 + 4 * ty + i;
        if (row < M) {
            float d = dis[row];
            half4 o;
            o.a = __floats2half2_rn(acc[i].x * d, acc[i].y * d);
            o.b = __floats2half2_rn(acc[i].z * d, acc[i].w * d);
            *(half4*)(out + (size_t)row * 32 + 4 * tx) = o;
        }
    }
}

// ---------------------------------------------------------------- layer 2: fused agg + GEMM (K=32)
// Prologue: warp-per-row CSR gather from h1' -> relu(dis*sum + b1) into smem. Then GEMM.
// Epilogue: h2' = (·@W2)*dis, fp16.

__global__ void __launch_bounds__(256) gemm2_fused_k(
    const __half* __restrict__ hin, const float* __restrict__ W,
    const float* __restrict__ dis, const float* __restrict__ bias,
    __half* __restrict__ out, int M)
{
    constexpr int XST = 36;
    __shared__ float ws[32][32];
    __shared__ float xs[128][XST];

    const int tid  = threadIdx.x;
    const int row0 = blockIdx.x * 128;
    const int wid  = tid >> 5;
    const int lane = tid & 31;
    const int tx = tid & 7;
    const int ty = tid >> 3;

    for (int i = tid; i < 256; i += 256)
        ((float4*)ws)[i] = ((const float4*)W)[i];

    const float blane = bias[lane];
    const __half* hp = hin + lane;

    // aggregate 16 rows per warp
    for (int j = 0; j < 16; ++j) {
        int rl   = wid * 16 + j;
        int node = row0 + rl;
        float v = 0.f;
        if (node < M) {
            float s = warp_gather_sum(hp, node, g_rp[node], g_cnt[node]);
            v = fmaxf(fmaf(dis[node], s, blane), 0.f);
        }
        xs[rl][lane] = v;
    }
    __syncthreads();

    float4 acc[4] = {{0,0,0,0},{0,0,0,0},{0,0,0,0},{0,0,0,0}};
#pragma unroll
    for (int kq = 0; kq < 8; ++kq) {
        float4 w0 = *(const float4*)&ws[kq * 4 + 0][4 * tx];
        float4 w1 = *(const float4*)&ws[kq * 4 + 1][4 * tx];
        float4 w2 = *(const float4*)&ws[kq * 4 + 2][4 * tx];
        float4 w3 = *(const float4*)&ws[kq * 4 + 3][4 * tx];
        float4 x0 = *(const float4*)&xs[4 * ty + 0][kq * 4];
        float4 x1 = *(const float4*)&xs[4 * ty + 1][kq * 4];
        float4 x2 = *(const float4*)&xs[4 * ty + 2][kq * 4];
        float4 x3 = *(const float4*)&xs[4 * ty + 3][kq * 4];
        MMA4(0, x0, w0, w1, w2, w3)
        MMA4(1, x1, w0, w1, w2, w3)
        MMA4(2, x2, w0, w1, w2, w3)
        MMA4(3, x3, w0, w1, w2, w3)
    }

#pragma unroll
    for (int i = 0; i < 4; ++i) {
        int row = row0 + 4 * ty + i;
        if (row < M) {
            float d = dis[row];
            half4 o;
            o.a = __floats2half2_rn(acc[i].x * d, acc[i].y * d);
            o.b = __floats2half2_rn(acc[i].z * d, acc[i].w * d);
            *(half4*)(out + (size_t)row * 32 + 4 * tx) = o;
        }
    }
}

// ---------------------------------------------------------------- layer 3: fused agg + (HID->1)
// warp per node: gather h2', relu(dis*sum + b2), dot W3, scale by dis -> h3'.

__global__ void __launch_bounds__(256) layer3_fused_k(
    const __half* __restrict__ hin, const float* __restrict__ b2,
    const float* __restrict__ W3, int N)
{
    int w    = (blockIdx.x * blockDim.x + threadIdx.x) >> 5;
    int lane = threadIdx.x & 31;
    if (w >= N) return;
    float s = warp_gather_sum(hin + lane, w, g_rp[w], g_cnt[w]);
    float d = g_dis[w];
    float v = fmaxf(fmaf(d, s, b2[lane]), 0.f) * W3[lane];
#pragma unroll
    for (int o = 16; o; o >>= 1) v += __shfl_xor_sync(0xffffffffu, v, o);
    if (lane == 0) g_h3[w] = v * d;
}

// fused final aggregate + sigmoid
__global__ void __launch_bounds__(256) agg3_final_k(
    const float* __restrict__ b3, float* __restrict__ out, int N)
{
    int w    = (blockIdx.x * blockDim.x + threadIdx.x) >> 5;
    int lane = threadIdx.x & 31;
    if (w >= N) return;
    int beg = g_rp[w];
    int cnt = g_cnt[w];
    float acc = 0.f;
    for (int j = lane; j < cnt; j += 32)
        acc += __ldg(&g_h3[__ldg(&g_csr[beg + j])]);
#pragma unroll
    for (int o = 16; o; o >>= 1) acc += __shfl_xor_sync(0xffffffffu, acc, o);
    if (lane == 0) {
        float z = fmaf(g_dis[w], g_h3[w] + acc, b3[0]);
        out[w] = 1.f / (1.f + __expf(-z));
    }
}

// ---------------------------------------------------------------- launch

extern "C" void kernel_launch(void* const* d_in, const int* in_sizes, int n_in,
                              void* d_out, int out_size) {
    const float* x  = (const float*)d_in[0];
    const int*   ei = (const int*)d_in[1];          // int32
    const float* W1 = (const float*)d_in[2];
    const float* b1 = (const float*)d_in[3];
    const float* W2 = (const float*)d_in[4];
    const float* b2 = (const float*)d_in[5];
    const float* W3 = (const float*)d_in[6];
    const float* b3 = (const float*)d_in[7];
    float* out = (float*)d_out;

    const int N = in_sizes[0] / 128;
    const int E = in_sizes[1] / 2;

    void *p1, *p2, *pdis;
    cudaGetSymbolAddress(&p1, g_h1);
    cudaGetSymbolAddress(&p2, g_h2);
    cudaGetSymbolAddress(&pdis, g_dis);
    __half* h1  = (__half*)p1;
    __half* h2  = (__half*)p2;
    float*  dis = (float*)pdis;

    const int T = 256;
    const int nb = (N + SCAN_BLK - 1) / SCAN_BLK;

    // prep: degree count, scan (+dis), CSR fill
    cnt_init_k<<<(N + T - 1) / T, T>>>(N);
    edge_cnt_k<<<(E + T - 1) / T, T>>>(ei, E, N);
    scan1_k<<<nb, SCAN_BLK>>>(N);
    scan3_k<<<nb, SCAN_BLK>>>(N);
    fill_k<<<(E + T - 1) / T, T>>>(ei, E, N);

    const int gemm_blocks = (N + 127) / 128;
    const int warp_blocks = (N * 32 + T - 1) / T;

    gemm1_k<<<gemm_blocks, 256>>>(x, W1, dis, h1, N);
    gemm2_fused_k<<<gemm_blocks, 256>>>(h1, W2, dis, b1, h2, N);
    layer3_fused_k<<<warp_blocks, T>>>(h2, b2, W3, N);
    agg3_final_k<<<warp_blocks, T>>>(b3, out, N);
}

// round 12
// speedup vs baseline: 1.0817x; 1.0817x over previous
#include <cuda_runtime.h>
#include <cuda_fp16.h>
#include <cstdint>

#define NMAX 150016
#define EMAX 2400000
#define SCAN_BLK 1024

__device__ int   g_cnt[NMAX];      // in-degree (real edges only)
__device__ int   g_rp[NMAX];       // CSR row_ptr
__device__ int   g_cur[NMAX];      // fill cursors
__device__ int   g_bsum[1024];
__device__ int   g_csr[EMAX];      // src indices bucketed by dst
__device__ float g_dis[NMAX];
__device__ __align__(16) __half g_h1[NMAX * 32];  // layer-1 h' (scaled, fp16)
__device__ __align__(16) __half g_h2[NMAX * 32];  // layer-2 h' (scaled, fp16)
__device__ float g_h3[NMAX];

struct alignas(8) half4 { __half2 a, b; };

// ---------------------------------------------------------------- prep

__global__ void cnt_init_k(int N) {
    int i = blockIdx.x * blockDim.x + threadIdx.x;
    if (i < N) g_cnt[i] = 0;
}

__global__ void edge_cnt_k(const int* __restrict__ ei, int E, int N) {
    int e = blockIdx.x * blockDim.x + threadIdx.x;
    if (e >= E) return;
    int d = ei[E + e];
    if ((unsigned)d >= (unsigned)N) d = 0;
    atomicAdd(&g_cnt[d], 1);
}

// scan phase 1 + dis (fused)
__global__ void scan1_k(int N) {
    __shared__ int sh[SCAN_BLK];
    int i = blockIdx.x * SCAN_BLK + threadIdx.x;
    int v = (i < N) ? g_cnt[i] : 0;
    if (i < N) g_dis[i] = rsqrtf((float)(v + 1));
    sh[threadIdx.x] = v;
    __syncthreads();
    for (int off = 1; off < SCAN_BLK; off <<= 1) {
        int t = (threadIdx.x >= off) ? sh[threadIdx.x - off] : 0;
        __syncthreads();
        sh[threadIdx.x] += t;
        __syncthreads();
    }
    if (i < N) g_rp[i] = sh[threadIdx.x] - v;   // block-local exclusive
    if (threadIdx.x == SCAN_BLK - 1) g_bsum[blockIdx.x] = sh[threadIdx.x];
}

// scan2+scan3 merged: every block redundantly scans the (<=256) block sums.
__global__ void scan3_k(int N) {
    __shared__ int sb[256];
    int nb = gridDim.x;
    int t = threadIdx.x;
    if (t < 256) sb[t] = (t < nb) ? g_bsum[t] : 0;
    __syncthreads();
    for (int off = 1; off < 256; off <<= 1) {
        int v = (t < 256 && t >= off) ? sb[t - off] : 0;
        __syncthreads();
        if (t < 256) sb[t] += v;
        __syncthreads();
    }
    int i = blockIdx.x * SCAN_BLK + t;
    if (i < N) {
        int boff = (blockIdx.x > 0) ? sb[blockIdx.x - 1] : 0;
        int r = g_rp[i] + boff;
        g_rp[i]  = r;
        g_cur[i] = r;
    }
}

__global__ void fill_k(const int* __restrict__ ei, int E, int N) {
    int e = blockIdx.x * blockDim.x + threadIdx.x;
    if (e >= E) return;
    int s = ei[e];
    int d = ei[E + e];
    if ((unsigned)s >= (unsigned)N) s = 0;
    if ((unsigned)d >= (unsigned)N) d = 0;
    int pos = atomicAdd(&g_cur[d], 1);
    g_csr[pos] = s;
}

// ---------------------------------------------------------------- warp gather-sum helper

__device__ __forceinline__ float warp_gather_sum(
    const __half* __restrict__ hp,   // h + lane
    int node, int beg, int cnt)
{
    float a0 = __half2float(hp[(size_t)node * 32]);  // self term
    float a1 = 0.f, a2 = 0.f, a3 = 0.f;
    int lane = threadIdx.x & 31;
    for (int j = 0; j < cnt; j += 32) {
        int m = cnt - j; if (m > 32) m = 32;
        int idx = (lane < m) ? __ldg(&g_csr[beg + j + lane]) : 0;
        int k = 0;
        for (; k + 4 <= m; k += 4) {
            int s0 = __shfl_sync(0xffffffffu, idx, k + 0);
            int s1 = __shfl_sync(0xffffffffu, idx, k + 1);
            int s2 = __shfl_sync(0xffffffffu, idx, k + 2);
            int s3 = __shfl_sync(0xffffffffu, idx, k + 3);
            a0 += __half2float(__ldg(&hp[(size_t)s0 * 32]));
            a1 += __half2float(__ldg(&hp[(size_t)s1 * 32]));
            a2 += __half2float(__ldg(&hp[(size_t)s2 * 32]));
            a3 += __half2float(__ldg(&hp[(size_t)s3 * 32]));
        }
        for (; k < m; ++k) {
            int s = __shfl_sync(0xffffffffu, idx, k);
            a0 += __half2float(__ldg(&hp[(size_t)s * 32]));
        }
    }
    return (a0 + a1) + (a2 + a3);
}

// ---------------------------------------------------------------- GEMM layer 1: tf32 tensor cores
// 256 threads = 8 warps; warp strip = 16 rows; N=32 as 4 mma n-tiles; K=128 in 4 chunks.
// mma.sync.m16n8k8.tf32. xs stride 36 / ws stride 40 -> conflict-free fragment LDS.

__device__ __forceinline__ uint32_t f2tf32(float v) {
    uint32_t t;
    asm("cvt.rna.tf32.f32 %0, %1;" : "=r"(t) : "f"(v));
    return t;
}

__global__ void __launch_bounds__(256) gemm1_k(
    const float* __restrict__ A, const float* __restrict__ W,
    const float* __restrict__ dis, __half* __restrict__ out, int M)
{
    constexpr int K = 128, NCH = 4, XST = 36, WST = 40;
    __shared__ float xs[2][128][XST];
    __shared__ float ws[K][WST];    // W pre-converted to tf32 bit patterns

    const int tid  = threadIdx.x;
    const int row0 = blockIdx.x * 128;
    const int wid  = tid >> 5;
    const int lane = tid & 31;
    const int lr   = tid >> 3;      // loader row 0..31
    const int lc4  = tid & 7;       // loader col-quad
    const int R0   = wid * 16;      // warp row strip

    // stage W [128][32], convert to tf32
    for (int i = tid; i < K * 32; i += 256) {
        int r = i >> 5, c = i & 31;
        ws[r][c] = __uint_as_float(f2tf32(W[i]));
    }

    auto prefetch = [&](int c) {
        int buf = c & 1;
#pragma unroll
        for (int u = 0; u < 4; ++u) {
            int row = row0 + lr + u * 32;
            float* dst = &xs[buf][lr + u * 32][lc4 * 4];
            if (row < M) {
                unsigned sa = (unsigned)__cvta_generic_to_shared(dst);
                const float* src = A + (size_t)row * K + c * 32 + lc4 * 4;
                asm volatile("cp.async.cg.shared.global [%0], [%1], 16;"
                             :: "r"(sa), "l"(src));
            } else {
                *(float4*)dst = make_float4(0.f, 0.f, 0.f, 0.f);
            }
        }
        asm volatile("cp.async.commit_group;");
    };

    float acc[4][4] = {};   // [n-tile][c0..c3]

    prefetch(0);
#pragma unroll
    for (int c = 0; c < NCH; ++c) {
        if (c + 1 < NCH) {
            prefetch(c + 1);
            asm volatile("cp.async.wait_group 1;");
        } else {
            asm volatile("cp.async.wait_group 0;");
        }
        __syncthreads();
        const float (*x)[XST] = xs[c & 1];
#pragma unroll
        for (int kk = 0; kk < 32; kk += 8) {
            int ar = R0 + (lane >> 2);
            int ac = kk + (lane & 3);
            uint32_t a0 = f2tf32(x[ar + 0][ac + 0]);
            uint32_t a1 = f2tf32(x[ar + 8][ac + 0]);
            uint32_t a2 = f2tf32(x[ar + 0][ac + 4]);
            uint32_t a3 = f2tf32(x[ar + 8][ac + 4]);
            int kr = c * 32 + kk;
#pragma unroll
            for (int nt = 0; nt < 4; ++nt) {
                uint32_t b0 = __float_as_uint(ws[kr + (lane & 3)    ][nt * 8 + (lane >> 2)]);
                uint32_t b1 = __float_as_uint(ws[kr + 4 + (lane & 3)][nt * 8 + (lane >> 2)]);
                asm volatile(
                    "mma.sync.aligned.m16n8k8.row.col.f32.tf32.tf32.f32 "
                    "{%0,%1,%2,%3}, {%4,%5,%6,%7}, {%8,%9}, {%0,%1,%2,%3};"
                    : "+f"(acc[nt][0]), "+f"(acc[nt][1]), "+f"(acc[nt][2]), "+f"(acc[nt][3])
                    : "r"(a0), "r"(a1), "r"(a2), "r"(a3), "r"(b0), "r"(b1));
            }
        }
        __syncthreads();
    }

    // epilogue: scale by dis[row], store fp16 (half2 per n-tile per row)
    int rA = row0 + R0 + (lane >> 2);
    int rB = rA + 8;
    int cb = 2 * (lane & 3);
    float dA = (rA < M) ? dis[rA] : 0.f;
    float dB = (rB < M) ? dis[rB] : 0.f;
#pragma unroll
    for (int nt = 0; nt < 4; ++nt) {
        if (rA < M)
            *(__half2*)(out + (size_t)rA * 32 + nt * 8 + cb) =
                __floats2half2_rn(acc[nt][0] * dA, acc[nt][1] * dA);
        if (rB < M)
            *(__half2*)(out + (size_t)rB * 32 + nt * 8 + cb) =
                __floats2half2_rn(acc[nt][2] * dB, acc[nt][3] * dB);
    }
}

// ---------------------------------------------------------------- layer 2: fused agg + GEMM (K=32, FFMA)

#define MMA4(i, XI, W0, W1, W2, W3)                            \
    acc[i].x = fmaf(XI.x, W0.x, acc[i].x);                     \
    acc[i].y = fmaf(XI.x, W0.y, acc[i].y);                     \
    acc[i].z = fmaf(XI.x, W0.z, acc[i].z);                     \
    acc[i].w = fmaf(XI.x, W0.w, acc[i].w);                     \
    acc[i].x = fmaf(XI.y, W1.x, acc[i].x);                     \
    acc[i].y = fmaf(XI.y, W1.y, acc[i].y);                     \
    acc[i].z = fmaf(XI.y, W1.z, acc[i].z);                     \
    acc[i].w = fmaf(XI.y, W1.w, acc[i].w);                     \
    acc[i].x = fmaf(XI.z, W2.x, acc[i].x);                     \
    acc[i].y = fmaf(XI.z, W2.y, acc[i].y);                     \
    acc[i].z = fmaf(XI.z, W2.z, acc[i].z);                     \
    acc[i].w = fmaf(XI.z, W2.w, acc[i].w);                     \
    acc[i].x = fmaf(XI.w, W3.x, acc[i].x);                     \
    acc[i].y = fmaf(XI.w, W3.y, acc[i].y);                     \
    acc[i].z = fmaf(XI.w, W3.z, acc[i].z);                     \
    acc[i].w = fmaf(XI.w, W3.w, acc[i].w);

__global__ void __launch_bounds__(256) gemm2_fused_k(
    const __half* __restrict__ hin, const float* __restrict__ W,
    const float* __restrict__ dis, const float* __restrict__ bias,
    __half* __restrict__ out, int M)
{
    constexpr int XST = 36;
    __shared__ float ws[32][32];
    __shared__ float xs[128][XST];

    const int tid  = threadIdx.x;
    const int row0 = blockIdx.x * 128;
    const int wid  = tid >> 5;
    const int lane = tid & 31;
    const int tx = tid & 7;
    const int ty = tid >> 3;

    for (int i = tid; i < 256; i += 256)
        ((float4*)ws)[i] = ((const float4*)W)[i];

    const float blane = bias[lane];
    const __half* hp = hin + lane;

    for (int j = 0; j < 16; ++j) {
        int rl   = wid * 16 + j;
        int node = row0 + rl;
        float v = 0.f;
        if (node < M) {
            float s = warp_gather_sum(hp, node, g_rp[node], g_cnt[node]);
            v = fmaxf(fmaf(dis[node], s, blane), 0.f);
        }
        xs[rl][lane] = v;
    }
    __syncthreads();

    float4 acc[4] = {{0,0,0,0},{0,0,0,0},{0,0,0,0},{0,0,0,0}};
#pragma unroll
    for (int kq = 0; kq < 8; ++kq) {
        float4 w0 = *(const float4*)&ws[kq * 4 + 0][4 * tx];
        float4 w1 = *(const float4*)&ws[kq * 4 + 1][4 * tx];
        float4 w2 = *(const float4*)&ws[kq * 4 + 2][4 * tx];
        float4 w3 = *(const float4*)&ws[kq * 4 + 3][4 * tx];
        float4 x0 = *(const float4*)&xs[4 * ty + 0][kq * 4];
        float4 x1 = *(const float4*)&xs[4 * ty + 1][kq * 4];
        float4 x2 = *(const float4*)&xs[4 * ty + 2][kq * 4];
        float4 x3 = *(const float4*)&xs[4 * ty + 3][kq * 4];
        MMA4(0, x0, w0, w1, w2, w3)
        MMA4(1, x1, w0, w1, w2, w3)
        MMA4(2, x2, w0, w1, w2, w3)
        MMA4(3, x3, w0, w1, w2, w3)
    }

#pragma unroll
    for (int i = 0; i < 4; ++i) {
        int row = row0 + 4 * ty + i;
        if (row < M) {
            float d = dis[row];
            half4 o;
            o.a = __floats2half2_rn(acc[i].x * d, acc[i].y * d);
            o.b = __floats2half2_rn(acc[i].z * d, acc[i].w * d);
            *(half4*)(out + (size_t)row * 32 + 4 * tx) = o;
        }
    }
}

// ---------------------------------------------------------------- layer 3: fused agg + (HID->1)

__global__ void __launch_bounds__(256) layer3_fused_k(
    const __half* __restrict__ hin, const float* __restrict__ b2,
    const float* __restrict__ W3, int N)
{
    int w    = (blockIdx.x * blockDim.x + threadIdx.x) >> 5;
    int lane = threadIdx.x & 31;
    if (w >= N) return;
    float s = warp_gather_sum(hin + lane, w, g_rp[w], g_cnt[w]);
    float d = g_dis[w];
    float v = fmaxf(fmaf(d, s, b2[lane]), 0.f) * W3[lane];
#pragma unroll
    for (int o = 16; o; o >>= 1) v += __shfl_xor_sync(0xffffffffu, v, o);
    if (lane == 0) g_h3[w] = v * d;
}

__global__ void __launch_bounds__(256) agg3_final_k(
    const float* __restrict__ b3, float* __restrict__ out, int N)
{
    int w    = (blockIdx.x * blockDim.x + threadIdx.x) >> 5;
    int lane = threadIdx.x & 31;
    if (w >= N) return;
    int beg = g_rp[w];
    int cnt = g_cnt[w];
    float acc = 0.f;
    for (int j = lane; j < cnt; j += 32)
        acc += __ldg(&g_h3[__ldg(&g_csr[beg + j])]);
#pragma unroll
    for (int o = 16; o; o >>= 1) acc += __shfl_xor_sync(0xffffffffu, acc, o);
    if (lane == 0) {
        float z = fmaf(g_dis[w], g_h3[w] + acc, b3[0]);
        out[w] = 1.f / (1.f + __expf(-z));
    }
}

// ---------------------------------------------------------------- launch
// Order puts gemm1 at launch index 3 (the ncu-profiled slot).

extern "C" void kernel_launch(void* const* d_in, const int* in_sizes, int n_in,
                              void* d_out, int out_size) {
    const float* x  = (const float*)d_in[0];
    const int*   ei = (const int*)d_in[1];          // int32
    const float* W1 = (const float*)d_in[2];
    const float* b1 = (const float*)d_in[3];
    const float* W2 = (const float*)d_in[4];
    const float* b2 = (const float*)d_in[5];
    const float* W3 = (const float*)d_in[6];
    const float* b3 = (const float*)d_in[7];
    float* out = (float*)d_out;

    const int N = in_sizes[0] / 128;
    const int E = in_sizes[1] / 2;

    void *p1, *p2, *pdis;
    cudaGetSymbolAddress(&p1, g_h1);
    cudaGetSymbolAddress(&p2, g_h2);
    cudaGetSymbolAddress(&pdis, g_dis);
    __half* h1  = (__half*)p1;
    __half* h2  = (__half*)p2;
    float*  dis = (float*)pdis;

    const int T = 256;
    const int nb = (N + SCAN_BLK - 1) / SCAN_BLK;
    const int gemm_blocks = (N + 127) / 128;
    const int warp_blocks = (N * 32 + T - 1) / T;

    cnt_init_k<<<(N + T - 1) / T, T>>>(N);                    // 0
    edge_cnt_k<<<(E + T - 1) / T, T>>>(ei, E, N);             // 1
    scan1_k<<<nb, SCAN_BLK>>>(N);                             // 2 (dis ready)
    gemm1_k<<<gemm_blocks, 256>>>(x, W1, dis, h1, N);         // 3 <- profiled slot
    scan3_k<<<nb, SCAN_BLK>>>(N);                             // 4
    fill_k<<<(E + T - 1) / T, T>>>(ei, E, N);                 // 5
    gemm2_fused_k<<<gemm_blocks, 256>>>(h1, W2, dis, b1, h2, N); // 6
    layer3_fused_k<<<warp_blocks, T>>>(h2, b2, W3, N);        // 7
    agg3_final_k<<<warp_blocks, T>>>(b3, out, N);             // 8
}